// round 1
// baseline (speedup 1.0000x reference)
#include <cuda_runtime.h>
#include <cstdint>

// Problem constants (fixed shapes from metadata)
#define BATCH 1024
#define DIM   512
#define NCLS  100000

#define BM 128   // batch tile
#define BN 128   // class tile
#define BK 32    // k tile
#define SPAD 136 // smem row stride (conflict-free: 136 % 32 == 8)

// scratch (static device arrays — no allocation)
__device__ float g_xn[BATCH * DIM];    // normalized input, pre-rounded to tf32
__device__ float g_winv[NCLS];         // 1 / max(||w_c||, eps)

__device__ __forceinline__ float tf32r(float x) {
    uint32_t u;
    asm("cvt.rna.tf32.f32 %0, %1;" : "=r"(u) : "f"(x));
    return __uint_as_float(u);
}

// ---------------- kernel 1: normalize input rows, round to tf32 ----------------
__global__ void k_norm_input(const float* __restrict__ x) {
    int row = blockIdx.x;
    int t = threadIdx.x;  // 128 threads, 4 floats each
    float4 v = *(const float4*)(x + row * DIM + t * 4);
    float ss = v.x * v.x + v.y * v.y + v.z * v.z + v.w * v.w;
    #pragma unroll
    for (int o = 16; o; o >>= 1) ss += __shfl_xor_sync(0xffffffffu, ss, o);
    __shared__ float ws[4];
    if ((t & 31) == 0) ws[t >> 5] = ss;
    __syncthreads();
    float tot = ws[0] + ws[1] + ws[2] + ws[3];
    float inv = 1.0f / fmaxf(sqrtf(tot), 1e-12f);
    float4 o4;
    o4.x = tf32r(v.x * inv);
    o4.y = tf32r(v.y * inv);
    o4.z = tf32r(v.z * inv);
    o4.w = tf32r(v.w * inv);
    *(float4*)(g_xn + row * DIM + t * 4) = o4;
}

// ---------------- kernel 2: weight row inverse norms ----------------
__global__ void k_winv(const float* __restrict__ w) {
    int row = blockIdx.x;
    int t = threadIdx.x;  // 128 threads
    float4 v = *(const float4*)(w + (size_t)row * DIM + t * 4);
    float ss = v.x * v.x + v.y * v.y + v.z * v.z + v.w * v.w;
    #pragma unroll
    for (int o = 16; o; o >>= 1) ss += __shfl_xor_sync(0xffffffffu, ss, o);
    __shared__ float ws[4];
    if ((t & 31) == 0) ws[t >> 5] = ss;
    __syncthreads();
    if (t == 0) {
        float tot = ws[0] + ws[1] + ws[2] + ws[3];
        g_winv[row] = 1.0f / fmaxf(sqrtf(tot), 1e-12f);
    }
}

// ---------------- epilogue math ----------------
__device__ __forceinline__ float arcface(float cosv, bool tgt) {
    if (!tgt) return 30.0f * cosv;
    float s2 = 1.0f - cosv * cosv;
    s2 = fminf(fmaxf(s2, 0.0f), 1.0f);
    float sine = sqrtf(s2);
    float phi = cosv * 0.8775825618903728f - sine * 0.479425538604203f;
    phi = (cosv > -0.8775825618903728f) ? phi : (cosv - 7.191383079063045f);
    return 30.0f * phi;
}

__device__ __forceinline__ void mma_tf32(float* d, const float* a, const float* b) {
    asm volatile(
        "mma.sync.aligned.m16n8k8.row.col.f32.tf32.tf32.f32 "
        "{%0,%1,%2,%3}, {%4,%5,%6,%7}, {%8,%9}, {%0,%1,%2,%3};\n"
        : "+f"(d[0]), "+f"(d[1]), "+f"(d[2]), "+f"(d[3])
        : "r"(__float_as_uint(a[0])), "r"(__float_as_uint(a[1])),
          "r"(__float_as_uint(a[2])), "r"(__float_as_uint(a[3])),
          "r"(__float_as_uint(b[0])), "r"(__float_as_uint(b[1])));
}

// ---------------- kernel 3: GEMM + fused ArcFace epilogue ----------------
// grid = (BATCH/BM = 8, ceil(NCLS/BN) = 782); x (b-tile) fastest so the 8 CTAs
// sharing a weight tile co-schedule -> weight served from L2 for 7 of 8.
__global__ __launch_bounds__(256) void k_gemm(
    const float* __restrict__ w,
    const int* __restrict__ label,
    float* __restrict__ out)
{
    __shared__ float As[BK][SPAD];   // k-major: As[k][b_row]
    __shared__ float Bs[BK][SPAD];   // k-major: Bs[k][c_row]
    __shared__ int   slabel[BM];
    __shared__ float swinv[BN];

    const int bbase = blockIdx.x * BM;
    const int cbase = blockIdx.y * BN;

    const int tid = threadIdx.x;
    const int lane = tid & 31;
    const int wid = tid >> 5;
    const int warp_b = (wid & 1) * 64;   // warp grid 2(b) x 4(c)
    const int warp_c = (wid >> 1) * 32;
    const int gid = lane >> 2;           // 0..7
    const int tig = lane & 3;            // 0..3

    float acc[4][4][4];
    #pragma unroll
    for (int i = 0; i < 4; i++)
        #pragma unroll
        for (int j = 0; j < 4; j++)
            #pragma unroll
            for (int k = 0; k < 4; k++) acc[i][j][k] = 0.0f;

    if (tid < BM) slabel[tid] = label[bbase + tid];
    if (tid < BN) {
        int c = cbase + tid;
        swinv[tid] = (c < NCLS) ? g_winv[c] : 0.0f;
    }

    for (int k0 = 0; k0 < DIM; k0 += BK) {
        __syncthreads();
        // Load A tile (already tf32-rounded). flat = tid + l*256; kq = flat>>7 (float4
        // index in k), row = flat&127. Within a warp row spans 32 distinct values ->
        // conflict-free transposed smem stores.
        #pragma unroll
        for (int l = 0; l < 4; l++) {
            int flat = tid + l * 256;
            int kq = flat >> 7;
            int row = flat & 127;
            float4 v = *(const float4*)(g_xn + (bbase + row) * DIM + k0 + kq * 4);
            As[kq * 4 + 0][row] = v.x;
            As[kq * 4 + 1][row] = v.y;
            As[kq * 4 + 2][row] = v.z;
            As[kq * 4 + 3][row] = v.w;
        }
        // Load B tile (raw weight -> tf32 rna round here; column norm applied in epilogue)
        #pragma unroll
        for (int l = 0; l < 4; l++) {
            int flat = tid + l * 256;
            int kq = flat >> 7;
            int row = flat & 127;
            int c = cbase + row;
            float4 v = make_float4(0.f, 0.f, 0.f, 0.f);
            if (c < NCLS) v = *(const float4*)(w + (size_t)c * DIM + k0 + kq * 4);
            Bs[kq * 4 + 0][row] = tf32r(v.x);
            Bs[kq * 4 + 1][row] = tf32r(v.y);
            Bs[kq * 4 + 2][row] = tf32r(v.z);
            Bs[kq * 4 + 3][row] = tf32r(v.w);
        }
        __syncthreads();

        #pragma unroll
        for (int kk = 0; kk < BK; kk += 8) {
            float afr[4][4];
            #pragma unroll
            for (int mt = 0; mt < 4; mt++) {
                int r0 = warp_b + mt * 16 + gid;
                afr[mt][0] = As[kk + tig][r0];
                afr[mt][1] = As[kk + tig][r0 + 8];
                afr[mt][2] = As[kk + tig + 4][r0];
                afr[mt][3] = As[kk + tig + 4][r0 + 8];
            }
            float bfr[4][2];
            #pragma unroll
            for (int nt = 0; nt < 4; nt++) {
                int c0 = warp_c + nt * 8 + gid;
                bfr[nt][0] = Bs[kk + tig][c0];
                bfr[nt][1] = Bs[kk + tig + 4][c0];
            }
            #pragma unroll
            for (int mt = 0; mt < 4; mt++)
                #pragma unroll
                for (int nt = 0; nt < 4; nt++)
                    mma_tf32(acc[mt][nt], afr[mt], bfr[nt]);
        }
    }

    // Fused ArcFace epilogue; float2 stores (c0/c1 adjacent -> full sectors)
    #pragma unroll
    for (int mt = 0; mt < 4; mt++) {
        int r = warp_b + mt * 16 + gid;
        int glb0 = bbase + r;
        int glb1 = glb0 + 8;
        int lab0 = slabel[r];
        int lab1 = slabel[r + 8];
        #pragma unroll
        for (int nt = 0; nt < 4; nt++) {
            int cloc = warp_c + nt * 8 + 2 * tig;
            int c = cbase + cloc;
            if (c >= NCLS) continue;  // c even, NCLS even -> c+1 valid when c < NCLS
            float wi0 = swinv[cloc];
            float wi1 = swinv[cloc + 1];
            float2 o0, o1;
            o0.x = arcface(acc[mt][nt][0] * wi0, lab0 == c);
            o0.y = arcface(acc[mt][nt][1] * wi1, lab0 == c + 1);
            o1.x = arcface(acc[mt][nt][2] * wi0, lab1 == c);
            o1.y = arcface(acc[mt][nt][3] * wi1, lab1 == c + 1);
            *(float2*)(out + (size_t)glb0 * NCLS + c) = o0;
            *(float2*)(out + (size_t)glb1 * NCLS + c) = o1;
        }
    }
}

extern "C" void kernel_launch(void* const* d_in, const int* in_sizes, int n_in,
                              void* d_out, int out_size) {
    const float* input  = (const float*)d_in[0];
    const int*   label  = (const int*)d_in[1];
    const float* weight = (const float*)d_in[2];
    float* out = (float*)d_out;

    k_norm_input<<<BATCH, 128>>>(input);
    k_winv<<<NCLS, 128>>>(weight);
    dim3 grid(BATCH / BM, (NCLS + BN - 1) / BN);
    k_gemm<<<grid, 256>>>(weight, label, out);
}

// round 4
// speedup vs baseline: 3.6209x; 3.6209x over previous
#include <cuda_runtime.h>
#include <cstdint>

// ---------------- problem constants ----------------
#define BATCH 1024
#define DIM   512
#define NCLS  100000

// ---------------- GEMM tiling ----------------
#define BM 128
#define BN 128
#define BK 32
#define NCHUNKS (DIM / BK)              // 16
#define STAGES 3
#define A_BYTES (BM * BK * 4)           // 16384
#define B_BYTES (BN * BK * 4)           // 16384
#define STAGE_BYTES (A_BYTES + B_BYTES) // 32768
#define DYN_SMEM (STAGES * STAGE_BYTES) // 98304

// scratch (static device arrays — no allocation)
__device__ float g_xn[BATCH * DIM];   // normalized input, tf32-rna pre-rounded
__device__ float g_winv[NCLS];        // 1 / max(||w_c||, eps)

// ---------------- helpers ----------------
__device__ __forceinline__ uint32_t smem_u32(const void* p) {
    uint32_t a;
    asm("{ .reg .u64 t; cvta.to.shared.u64 t, %1; cvt.u32.u64 %0, t; }" : "=r"(a) : "l"(p));
    return a;
}
__device__ __forceinline__ float tf32r(float x) {
    uint32_t u;
    asm("cvt.rna.tf32.f32 %0, %1;" : "=r"(u) : "f"(x));
    return __uint_as_float(u);
}
__device__ __forceinline__ void cp16(uint32_t saddr, const void* g, bool valid) {
    int sz = valid ? 16 : 0;
    asm volatile("cp.async.cg.shared.global.L2::128B [%0], [%1], 16, %2;\n"
                 :: "r"(saddr), "l"(g), "r"(sz) : "memory");
}
__device__ __forceinline__ void ldsm_x4(uint32_t* r, uint32_t addr) {
    asm volatile("ldmatrix.sync.aligned.m8n8.x4.shared.b16 {%0,%1,%2,%3}, [%4];"
                 : "=r"(r[0]), "=r"(r[1]), "=r"(r[2]), "=r"(r[3]) : "r"(addr));
}
__device__ __forceinline__ void mma_tf32(float* d, const uint32_t* a, const uint32_t* b) {
    asm volatile(
        "mma.sync.aligned.m16n8k8.row.col.f32.tf32.tf32.f32 "
        "{%0,%1,%2,%3}, {%4,%5,%6,%7}, {%8,%9}, {%0,%1,%2,%3};\n"
        : "+f"(d[0]), "+f"(d[1]), "+f"(d[2]), "+f"(d[3])
        : "r"(a[0]), "r"(a[1]), "r"(a[2]), "r"(a[3]), "r"(b[0]), "r"(b[1]));
}

// ---------------- kernel 1: normalize input rows -> tf32-rna ----------------
__global__ void k_norm_input(const float* __restrict__ x) {
    int row = blockIdx.x;
    int t = threadIdx.x;  // 128 threads, 4 floats each
    float4 v = *(const float4*)(x + row * DIM + t * 4);
    float ss = v.x * v.x + v.y * v.y + v.z * v.z + v.w * v.w;
    #pragma unroll
    for (int o = 16; o; o >>= 1) ss += __shfl_xor_sync(0xffffffffu, ss, o);
    __shared__ float ws[4];
    if ((t & 31) == 0) ws[t >> 5] = ss;
    __syncthreads();
    float tot = ws[0] + ws[1] + ws[2] + ws[3];
    float inv = 1.0f / fmaxf(sqrtf(tot), 1e-12f);
    float4 o4;
    o4.x = tf32r(v.x * inv);
    o4.y = tf32r(v.y * inv);
    o4.z = tf32r(v.z * inv);
    o4.w = tf32r(v.w * inv);
    *(float4*)(g_xn + row * DIM + t * 4) = o4;
}

// ---------------- kernel 2: weight row inverse norms ----------------
__global__ void k_winv(const float* __restrict__ w) {
    int row = blockIdx.x;
    int t = threadIdx.x;  // 128 threads
    float4 v = *(const float4*)(w + (size_t)row * DIM + t * 4);
    float ss = v.x * v.x + v.y * v.y + v.z * v.z + v.w * v.w;
    #pragma unroll
    for (int o = 16; o; o >>= 1) ss += __shfl_xor_sync(0xffffffffu, ss, o);
    __shared__ float ws[4];
    if ((t & 31) == 0) ws[t >> 5] = ss;
    __syncthreads();
    if (t == 0) {
        float tot = ws[0] + ws[1] + ws[2] + ws[3];
        g_winv[row] = 1.0f / fmaxf(sqrtf(tot), 1e-12f);
    }
}

// ---------------- ArcFace epilogue math ----------------
__device__ __forceinline__ float arcface(float cosv, bool tgt) {
    if (!tgt) return 30.0f * cosv;
    float s2 = fminf(fmaxf(1.0f - cosv * cosv, 0.0f), 1.0f);
    float sine = sqrtf(s2);
    float phi = cosv * 0.8775825618903728f - sine * 0.479425538604203f;
    phi = (cosv > -0.8775825618903728f) ? phi : (cosv - 7.191383079063045f);
    return 30.0f * phi;
}

// ---------------- kernel 3: pipelined tf32 mma.sync GEMM + fused ArcFace ----------------
// SMEM layout per stage: A[128 rows][32 k] then B[128 rows][32 k], 128B rows,
// 16B chunks swizzled by (q ^ (row&7)) — conflict-free for both cp.async stores
// and ldmatrix reads.
// grid = (8 btiles, 782 ctiles); x fastest -> 8 CTAs share a weight tile via L2.
__global__ void __launch_bounds__(256, 2) k_gemm(
    const float* __restrict__ w,
    const int* __restrict__ label,
    float* __restrict__ out)
{
    extern __shared__ __align__(128) char dyn[];
    __shared__ int s_label[BM];
    __shared__ float s_winv[BN];

    const int tid = threadIdx.x;
    const int lane = tid & 31;
    const int wid = tid >> 5;
    const int bbase = blockIdx.x * BM;
    const int cbase = blockIdx.y * BN;
    const uint32_t sbase = smem_u32(dyn);

    // warp grid 2(b) x 4(c): each warp computes 64 x 32
    const int warp_b = (wid & 1) * 64;
    const int warp_c = (wid >> 1) * 32;
    const int gid = lane >> 2;
    const int tig = lane & 3;
    const int rx = lane & 7;            // swizzle term (row & 7) for ldmatrix lanes

    // ldmatrix lane->row/col assignments (see fragment-layout derivation)
    const int a_row = (lane & 15);              // + warp_b + mt*16
    const int a_cq = (lane >> 4);               // + kk/4
    const int b_row = ((lane >> 4) << 3) + (lane & 7);  // + warp_c + pair*16
    const int b_cq = ((lane >> 3) & 1);         // + kk/4

    float acc[4][4][4];
    #pragma unroll
    for (int i = 0; i < 4; i++)
        #pragma unroll
        for (int j = 0; j < 4; j++)
            #pragma unroll
            for (int k = 0; k < 4; k++) acc[i][j][k] = 0.0f;

    if (tid < BM) s_label[tid] = label[bbase + tid];
    if (tid < BN) {
        int c = cbase + tid;
        s_winv[tid] = (c < NCLS) ? g_winv[c] : 0.0f;
    }

    // ---- stage loader: 2048 x 16B cp.async, 8 per thread ----
    auto load_stage = [&](int st, int k0) {
        const uint32_t ab = sbase + st * STAGE_BYTES;
        #pragma unroll
        for (int l = 0; l < 4; l++) {           // A: ops 0..1023
            int op = tid + l * 256;
            int r = op >> 3, q = op & 7;
            uint32_t sa = ab + r * 128 + ((q ^ (r & 7)) << 4);
            cp16(sa, g_xn + (bbase + r) * DIM + k0 + q * 4, true);
        }
        #pragma unroll
        for (int l = 0; l < 4; l++) {           // B: ops 0..1023
            int op = tid + l * 256;
            int r = op >> 3, q = op & 7;
            int cc = cbase + r;
            uint32_t sa = ab + A_BYTES + r * 128 + ((q ^ (r & 7)) << 4);
            cp16(sa, w + (size_t)cc * DIM + k0 + q * 4, cc < NCLS);
        }
    };

    // prologue: fill stages 0..STAGES-2
    load_stage(0, 0);
    asm volatile("cp.async.commit_group;" ::: "memory");
    load_stage(1, BK);
    asm volatile("cp.async.commit_group;" ::: "memory");

    for (int c = 0; c < NCHUNKS; c++) {
        asm volatile("cp.async.wait_group 1;" ::: "memory");
        __syncthreads();

        // issue next stage's loads first so the transfer overlaps this compute
        if (c + STAGES - 1 < NCHUNKS)
            load_stage((c + STAGES - 1) % STAGES, (c + STAGES - 1) * BK);
        asm volatile("cp.async.commit_group;" ::: "memory");

        const int st = c % STAGES;
        const uint32_t a_stage = sbase + st * STAGE_BYTES;
        const uint32_t b_stage = a_stage + A_BYTES;

        #pragma unroll
        for (int kk = 0; kk < BK; kk += 8) {
            const int kq = kk >> 2;
            // B fragments: 2 ldmatrix.x4, each covers two 8-n groups
            uint32_t bf[2][4];
            #pragma unroll
            for (int p = 0; p < 2; p++) {
                int r = warp_c + p * 16 + b_row;
                uint32_t addr = b_stage + r * 128 + ((((kq + b_cq) ^ rx) & 7) << 4);
                ldsm_x4(bf[p], addr);
            }
            // A fragments + MMAs
            #pragma unroll
            for (int mt = 0; mt < 4; mt++) {
                int r = warp_b + mt * 16 + a_row;
                uint32_t addr = a_stage + r * 128 + ((((kq + a_cq) ^ rx) & 7) << 4);
                uint32_t af[4];
                ldsm_x4(af, addr);
                #pragma unroll
                for (int nt = 0; nt < 4; nt++)
                    mma_tf32(acc[mt][nt], af, &bf[nt >> 1][(nt & 1) * 2]);
            }
        }
        __syncthreads();
    }

    // ---- fused ArcFace epilogue; float2 stores ----
    #pragma unroll
    for (int mt = 0; mt < 4; mt++) {
        int r = warp_b + mt * 16 + gid;
        int glb0 = bbase + r;
        int glb1 = glb0 + 8;
        int lab0 = s_label[r];
        int lab1 = s_label[r + 8];
        #pragma unroll
        for (int nt = 0; nt < 4; nt++) {
            int cloc = warp_c + nt * 8 + 2 * tig;
            int c = cbase + cloc;
            if (c >= NCLS) continue;  // c even, NCLS even -> c+1 valid when c < NCLS
            float wi0 = s_winv[cloc];
            float wi1 = s_winv[cloc + 1];
            float2 o0, o1;
            o0.x = arcface(acc[mt][nt][0] * wi0, lab0 == c);
            o0.y = arcface(acc[mt][nt][1] * wi1, lab0 == c + 1);
            o1.x = arcface(acc[mt][nt][2] * wi0, lab1 == c);
            o1.y = arcface(acc[mt][nt][3] * wi1, lab1 == c + 1);
            *(float2*)(out + (size_t)glb0 * NCLS + c) = o0;
            *(float2*)(out + (size_t)glb1 * NCLS + c) = o1;
        }
    }
}

extern "C" void kernel_launch(void* const* d_in, const int* in_sizes, int n_in,
                              void* d_out, int out_size) {
    const float* input  = (const float*)d_in[0];
    const int*   label  = (const int*)d_in[1];
    const float* weight = (const float*)d_in[2];
    float* out = (float*)d_out;

    cudaFuncSetAttribute(k_gemm, cudaFuncAttributeMaxDynamicSharedMemorySize, DYN_SMEM);

    k_norm_input<<<BATCH, 128>>>(input);
    k_winv<<<NCLS, 128>>>(weight);
    dim3 grid(BATCH / BM, (NCLS + BN - 1) / BN);
    k_gemm<<<grid, 256, DYN_SMEM>>>(weight, label, out);
}

// round 5
// speedup vs baseline: 3.6781x; 1.0158x over previous
#include <cuda_runtime.h>
#include <cuda_fp16.h>
#include <cstdint>

// ---------------- problem constants ----------------
#define BATCH 1024
#define DIM   512
#define NCLS  100000

// ---------------- GEMM tiling ----------------
#define BM 128
#define BN 128
#define BK 64                            // fp16: 64 k per chunk
#define NCHUNKS (DIM / BK)               // 8
#define STAGES 3
#define A_BYTES (BM * BK * 2)            // 16384
#define B_BYTES (BN * BK * 2)            // 16384
#define STAGE_BYTES (A_BYTES + B_BYTES)  // 32768
#define DYN_SMEM (STAGES * STAGE_BYTES)  // 98304

// scratch (static device arrays — no allocation)
__device__ __half g_xh[BATCH * DIM];            // normalized input, fp16-rna
__device__ __half g_wh[(size_t)NCLS * DIM];     // normalized weight, fp16-rna (102 MB)

// ---------------- helpers ----------------
__device__ __forceinline__ uint32_t smem_u32(const void* p) {
    uint32_t a;
    asm("{ .reg .u64 t; cvta.to.shared.u64 t, %1; cvt.u32.u64 %0, t; }" : "=r"(a) : "l"(p));
    return a;
}
__device__ __forceinline__ void cp16(uint32_t saddr, const void* g, bool valid) {
    int sz = valid ? 16 : 0;
    asm volatile("cp.async.cg.shared.global.L2::128B [%0], [%1], 16, %2;\n"
                 :: "r"(saddr), "l"(g), "r"(sz) : "memory");
}
__device__ __forceinline__ void ldsm_x4(uint32_t* r, uint32_t addr) {
    asm volatile("ldmatrix.sync.aligned.m8n8.x4.shared.b16 {%0,%1,%2,%3}, [%4];"
                 : "=r"(r[0]), "=r"(r[1]), "=r"(r[2]), "=r"(r[3]) : "r"(addr));
}
// m16n8k16 fp16 MMA, fp32 accumulate
__device__ __forceinline__ void mma_f16(float* d, const uint32_t* a, uint32_t b0, uint32_t b1) {
    asm volatile(
        "mma.sync.aligned.m16n8k16.row.col.f32.f16.f16.f32 "
        "{%0,%1,%2,%3}, {%4,%5,%6,%7}, {%8,%9}, {%0,%1,%2,%3};\n"
        : "+f"(d[0]), "+f"(d[1]), "+f"(d[2]), "+f"(d[3])
        : "r"(a[0]), "r"(a[1]), "r"(a[2]), "r"(a[3]), "r"(b0), "r"(b1));
}

// ---------------- kernel 1: normalize input rows -> fp16 ----------------
__global__ void k_norm_input(const float* __restrict__ x) {
    int row = blockIdx.x;
    int t = threadIdx.x;  // 128 threads, 4 floats each
    float4 v = *(const float4*)(x + row * DIM + t * 4);
    float ss = v.x * v.x + v.y * v.y + v.z * v.z + v.w * v.w;
    #pragma unroll
    for (int o = 16; o; o >>= 1) ss += __shfl_xor_sync(0xffffffffu, ss, o);
    __shared__ float ws[4];
    if ((t & 31) == 0) ws[t >> 5] = ss;
    __syncthreads();
    float tot = ws[0] + ws[1] + ws[2] + ws[3];
    float inv = 1.0f / fmaxf(sqrtf(tot), 1e-12f);
    __half2 h0 = __floats2half2_rn(v.x * inv, v.y * inv);
    __half2 h1 = __floats2half2_rn(v.z * inv, v.w * inv);
    uint2 pk;
    pk.x = *(uint32_t*)&h0;
    pk.y = *(uint32_t*)&h1;
    *(uint2*)(g_xh + row * DIM + t * 4) = pk;
}

// ---------------- kernel 2: normalize weight rows -> fp16 ----------------
__global__ void k_wnorm(const float* __restrict__ w) {
    int row = blockIdx.x;
    int t = threadIdx.x;  // 128 threads
    float4 v = *(const float4*)(w + (size_t)row * DIM + t * 4);
    float ss = v.x * v.x + v.y * v.y + v.z * v.z + v.w * v.w;
    #pragma unroll
    for (int o = 16; o; o >>= 1) ss += __shfl_xor_sync(0xffffffffu, ss, o);
    __shared__ float ws[4];
    if ((t & 31) == 0) ws[t >> 5] = ss;
    __syncthreads();
    float tot = ws[0] + ws[1] + ws[2] + ws[3];
    float inv = 1.0f / fmaxf(sqrtf(tot), 1e-12f);
    __half2 h0 = __floats2half2_rn(v.x * inv, v.y * inv);
    __half2 h1 = __floats2half2_rn(v.z * inv, v.w * inv);
    uint2 pk;
    pk.x = *(uint32_t*)&h0;
    pk.y = *(uint32_t*)&h1;
    *(uint2*)(g_wh + (size_t)row * DIM + t * 4) = pk;
}

// ---------------- ArcFace epilogue math ----------------
__device__ __forceinline__ float arcface(float cosv, bool tgt) {
    if (!tgt) return 30.0f * cosv;
    float s2 = fminf(fmaxf(1.0f - cosv * cosv, 0.0f), 1.0f);
    float sine = sqrtf(s2);
    float phi = cosv * 0.8775825618903728f - sine * 0.479425538604203f;
    phi = (cosv > -0.8775825618903728f) ? phi : (cosv - 7.191383079063045f);
    return 30.0f * phi;
}

// ---------------- kernel 3: pipelined fp16 mma.sync GEMM + fused ArcFace ----------------
// SMEM per stage: A[128 rows][64 k fp16] then B[128 rows][64 k fp16]; 128B rows,
// 16B chunks swizzled by (q ^ (row&7)) — conflict-free for cp.async stores and
// ldmatrix reads.
// grid = (8 btiles, 782 ctiles); x fastest -> 8 CTAs share a weight tile via L2.
__global__ void __launch_bounds__(256, 2) k_gemm(
    const int* __restrict__ label,
    float* __restrict__ out)
{
    extern __shared__ __align__(128) char dyn[];
    __shared__ int s_label[BM];

    const int tid = threadIdx.x;
    const int lane = tid & 31;
    const int wid = tid >> 5;
    const int bbase = blockIdx.x * BM;
    const int cbase = blockIdx.y * BN;
    const uint32_t sbase = smem_u32(dyn);

    // warp grid 2(b) x 4(c): each warp computes 64 x 32
    const int warp_b = (wid & 1) * 64;
    const int warp_c = (wid >> 1) * 32;
    const int gid = lane >> 2;
    const int tig = lane & 3;

    // fp16 ldmatrix.x4 lane mapping (identical for A and B operands):
    // row-in-16 = lane&15, k-chunk(16B) = lane>>4
    const int frow = lane & 15;
    const int fcq = lane >> 4;

    float acc[4][4][4];
    #pragma unroll
    for (int i = 0; i < 4; i++)
        #pragma unroll
        for (int j = 0; j < 4; j++)
            #pragma unroll
            for (int k = 0; k < 4; k++) acc[i][j][k] = 0.0f;

    if (tid < BM) s_label[tid] = label[bbase + tid];

    // ---- stage loader: 2048 x 16B cp.async, 8 per thread ----
    auto load_stage = [&](int st, int k0) {
        const uint32_t ab = sbase + st * STAGE_BYTES;
        #pragma unroll
        for (int l = 0; l < 4; l++) {           // A: 1024 ops
            int op = tid + l * 256;
            int r = op >> 3, q = op & 7;        // q: 16B chunk = 8 fp16
            uint32_t sa = ab + r * 128 + ((q ^ (r & 7)) << 4);
            cp16(sa, g_xh + (bbase + r) * DIM + k0 + q * 8, true);
        }
        #pragma unroll
        for (int l = 0; l < 4; l++) {           // B: 1024 ops
            int op = tid + l * 256;
            int r = op >> 3, q = op & 7;
            int cc = cbase + r;
            uint32_t sa = ab + A_BYTES + r * 128 + ((q ^ (r & 7)) << 4);
            cp16(sa, g_wh + (size_t)cc * DIM + k0 + q * 8, cc < NCLS);
        }
    };

    // prologue: fill stages 0..STAGES-2
    load_stage(0, 0);
    asm volatile("cp.async.commit_group;" ::: "memory");
    load_stage(1, BK);
    asm volatile("cp.async.commit_group;" ::: "memory");

    for (int c = 0; c < NCHUNKS; c++) {
        asm volatile("cp.async.wait_group 1;" ::: "memory");
        __syncthreads();

        // issue next stage's loads first so the transfer overlaps this compute
        if (c + STAGES - 1 < NCHUNKS)
            load_stage((c + STAGES - 1) % STAGES, (c + STAGES - 1) * BK);
        asm volatile("cp.async.commit_group;" ::: "memory");

        const int st = c % STAGES;
        const uint32_t a_stage = sbase + st * STAGE_BYTES;
        const uint32_t b_stage = a_stage + A_BYTES;

        #pragma unroll
        for (int s = 0; s < 4; s++) {           // 4 x k16 steps per 64-chunk
            const int q = 2 * s + fcq;          // 16B chunk within row
            // B fragments: 2 ldmatrix.x4, each covers 16 n x 16 k
            // regs: r0=[n0-7,k0-7] r1=[n8-15,k0-7] r2=[n0-7,k8-15] r3=[n8-15,k8-15]
            uint32_t bf[2][4];
            #pragma unroll
            for (int p = 0; p < 2; p++) {
                int r = warp_c + p * 16 + frow;
                uint32_t addr = b_stage + r * 128 + (((q ^ (r & 7)) & 7) << 4);
                ldsm_x4(bf[p], addr);
            }
            // A fragments + MMAs
            #pragma unroll
            for (int mt = 0; mt < 4; mt++) {
                int r = warp_b + mt * 16 + frow;
                uint32_t addr = a_stage + r * 128 + (((q ^ (r & 7)) & 7) << 4);
                uint32_t af[4];
                ldsm_x4(af, addr);
                #pragma unroll
                for (int nt = 0; nt < 4; nt++)
                    mma_f16(acc[mt][nt], af, bf[nt >> 1][nt & 1], bf[nt >> 1][(nt & 1) + 2]);
            }
        }
        __syncthreads();
    }

    // ---- fused ArcFace epilogue (weights pre-normalized: acc IS the cosine) ----
    #pragma unroll
    for (int mt = 0; mt < 4; mt++) {
        int r = warp_b + mt * 16 + gid;
        int glb0 = bbase + r;
        int glb1 = glb0 + 8;
        int lab0 = s_label[r];
        int lab1 = s_label[r + 8];
        #pragma unroll
        for (int nt = 0; nt < 4; nt++) {
            int c = cbase + warp_c + nt * 8 + 2 * tig;
            if (c >= NCLS) continue;  // c even, NCLS even -> c+1 valid when c < NCLS
            float2 o0, o1;
            o0.x = arcface(acc[mt][nt][0], lab0 == c);
            o0.y = arcface(acc[mt][nt][1], lab0 == c + 1);
            o1.x = arcface(acc[mt][nt][2], lab1 == c);
            o1.y = arcface(acc[mt][nt][3], lab1 == c + 1);
            *(float2*)(out + (size_t)glb0 * NCLS + c) = o0;
            *(float2*)(out + (size_t)glb1 * NCLS + c) = o1;
        }
    }
}

extern "C" void kernel_launch(void* const* d_in, const int* in_sizes, int n_in,
                              void* d_out, int out_size) {
    const float* input  = (const float*)d_in[0];
    const int*   label  = (const int*)d_in[1];
    const float* weight = (const float*)d_in[2];
    float* out = (float*)d_out;

    cudaFuncSetAttribute(k_gemm, cudaFuncAttributeMaxDynamicSharedMemorySize, DYN_SMEM);

    k_norm_input<<<BATCH, 128>>>(input);
    k_wnorm<<<NCLS, 128>>>(weight);
    dim3 grid(BATCH / BM, (NCLS + BN - 1) / BN);
    k_gemm<<<grid, 256, DYN_SMEM>>>(label, out);
}

// round 6
// speedup vs baseline: 4.0592x; 1.1036x over previous
#include <cuda_runtime.h>
#include <cuda_fp16.h>
#include <cstdint>

// ---------------- problem constants ----------------
#define BATCH 1024
#define DIM   512
#define NCLS  100000

// ---------------- GEMM tiling ----------------
#define BM 128
#define BN 128
#define BK 64                            // fp16: 64 k per chunk
#define NCHUNKS (DIM / BK)               // 8
#define STAGES 4
#define A_BYTES (BM * BK * 2)            // 16384
#define B_BYTES (BN * BK * 2)            // 16384
#define STAGE_BYTES (A_BYTES + B_BYTES)  // 32768
#define DYN_SMEM (STAGES * STAGE_BYTES)  // 131072
#define NTHREADS 512

// scratch (static device arrays — no allocation)
__device__ __half g_xh[BATCH * DIM];            // normalized input, fp16-rn
__device__ __half g_wh[(size_t)NCLS * DIM];     // normalized weight, fp16-rn (102 MB)

// ---------------- helpers ----------------
__device__ __forceinline__ uint32_t smem_u32(const void* p) {
    uint32_t a;
    asm("{ .reg .u64 t; cvta.to.shared.u64 t, %1; cvt.u32.u64 %0, t; }" : "=r"(a) : "l"(p));
    return a;
}
__device__ __forceinline__ void cp16(uint32_t saddr, const void* g, bool valid) {
    int sz = valid ? 16 : 0;
    asm volatile("cp.async.cg.shared.global.L2::128B [%0], [%1], 16, %2;\n"
                 :: "r"(saddr), "l"(g), "r"(sz) : "memory");
}
__device__ __forceinline__ void ldsm_x4(uint32_t* r, uint32_t addr) {
    asm volatile("ldmatrix.sync.aligned.m8n8.x4.shared.b16 {%0,%1,%2,%3}, [%4];"
                 : "=r"(r[0]), "=r"(r[1]), "=r"(r[2]), "=r"(r[3]) : "r"(addr));
}
// m16n8k16 fp16 MMA, fp16 accumulate (2x rate vs f32 acc)
__device__ __forceinline__ void mma_f16acc(uint32_t* d, const uint32_t* a, uint32_t b0, uint32_t b1) {
    asm volatile(
        "mma.sync.aligned.m16n8k16.row.col.f16.f16.f16.f16 "
        "{%0,%1}, {%2,%3,%4,%5}, {%6,%7}, {%0,%1};\n"
        : "+r"(d[0]), "+r"(d[1])
        : "r"(a[0]), "r"(a[1]), "r"(a[2]), "r"(a[3]), "r"(b0), "r"(b1));
}

// ---------------- kernel 1: normalize input rows -> fp16 ----------------
__global__ void k_norm_input(const float* __restrict__ x) {
    int row = blockIdx.x;
    int t = threadIdx.x;  // 128 threads, 4 floats each
    float4 v = *(const float4*)(x + row * DIM + t * 4);
    float ss = v.x * v.x + v.y * v.y + v.z * v.z + v.w * v.w;
    #pragma unroll
    for (int o = 16; o; o >>= 1) ss += __shfl_xor_sync(0xffffffffu, ss, o);
    __shared__ float ws[4];
    if ((t & 31) == 0) ws[t >> 5] = ss;
    __syncthreads();
    float tot = ws[0] + ws[1] + ws[2] + ws[3];
    float inv = 1.0f / fmaxf(sqrtf(tot), 1e-12f);
    __half2 h0 = __floats2half2_rn(v.x * inv, v.y * inv);
    __half2 h1 = __floats2half2_rn(v.z * inv, v.w * inv);
    uint2 pk;
    pk.x = *(uint32_t*)&h0;
    pk.y = *(uint32_t*)&h1;
    *(uint2*)(g_xh + row * DIM + t * 4) = pk;
}

// ---------------- kernel 2: normalize weight rows -> fp16 ----------------
__global__ void k_wnorm(const float* __restrict__ w) {
    int row = blockIdx.x;
    int t = threadIdx.x;  // 128 threads
    float4 v = *(const float4*)(w + (size_t)row * DIM + t * 4);
    float ss = v.x * v.x + v.y * v.y + v.z * v.z + v.w * v.w;
    #pragma unroll
    for (int o = 16; o; o >>= 1) ss += __shfl_xor_sync(0xffffffffu, ss, o);
    __shared__ float ws[4];
    if ((t & 31) == 0) ws[t >> 5] = ss;
    __syncthreads();
    float tot = ws[0] + ws[1] + ws[2] + ws[3];
    float inv = 1.0f / fmaxf(sqrtf(tot), 1e-12f);
    __half2 h0 = __floats2half2_rn(v.x * inv, v.y * inv);
    __half2 h1 = __floats2half2_rn(v.z * inv, v.w * inv);
    uint2 pk;
    pk.x = *(uint32_t*)&h0;
    pk.y = *(uint32_t*)&h1;
    *(uint2*)(g_wh + (size_t)row * DIM + t * 4) = pk;
}

// ---------------- ArcFace epilogue math ----------------
__device__ __forceinline__ float arcface(float cosv, bool tgt) {
    if (!tgt) return 30.0f * cosv;
    float s2 = fminf(fmaxf(1.0f - cosv * cosv, 0.0f), 1.0f);
    float sine = sqrtf(s2);
    float phi = cosv * 0.8775825618903728f - sine * 0.479425538604203f;
    phi = (cosv > -0.8775825618903728f) ? phi : (cosv - 7.191383079063045f);
    return 30.0f * phi;
}

// ---------------- kernel 3: pipelined fp16 GEMM (f16 acc + f32 chunk flush) ----------------
// 512 threads, 16 warps in a 4(b) x 4(c) grid of 32x32 warp tiles.
// SMEM per stage: A[128 rows][64 k] then B[128 rows][64 k], 128B rows, 16B chunks
// swizzled by (q ^ (row&7)).
// grid = (8 btiles, 782 ctiles); x fastest -> 8 CTAs share a weight tile via L2.
__global__ void __launch_bounds__(NTHREADS, 1) k_gemm(
    const int* __restrict__ label,
    float* __restrict__ out)
{
    extern __shared__ __align__(128) char dyn[];
    __shared__ int s_label[BM];

    const int tid = threadIdx.x;
    const int lane = tid & 31;
    const int wid = tid >> 5;
    const int bbase = blockIdx.x * BM;
    const int cbase = blockIdx.y * BN;
    const uint32_t sbase = smem_u32(dyn);

    // warp grid 4(b) x 4(c): each warp computes 32 x 32
    const int warp_b = (wid & 3) * 32;
    const int warp_c = (wid >> 2) * 32;
    const int gid = lane >> 2;
    const int tig = lane & 3;

    // fp16 ldmatrix.x4 lane mapping: row-in-16 = lane&15, 16B k-chunk = lane>>4
    const int frow = lane & 15;
    const int fcq = lane >> 4;

    float acc[2][4][4];
    #pragma unroll
    for (int i = 0; i < 2; i++)
        #pragma unroll
        for (int j = 0; j < 4; j++)
            #pragma unroll
            for (int k = 0; k < 4; k++) acc[i][j][k] = 0.0f;

    if (tid < BM) s_label[tid] = label[bbase + tid];

    // ---- stage loader: 2048 x 16B cp.async, 4 per thread ----
    auto load_stage = [&](int st, int k0) {
        const uint32_t ab = sbase + st * STAGE_BYTES;
        #pragma unroll
        for (int l = 0; l < 2; l++) {           // A: 1024 ops
            int op = tid + l * NTHREADS;
            int r = op >> 3, q = op & 7;        // q: 16B chunk = 8 fp16
            uint32_t sa = ab + r * 128 + ((q ^ (r & 7)) << 4);
            cp16(sa, g_xh + (bbase + r) * DIM + k0 + q * 8, true);
        }
        #pragma unroll
        for (int l = 0; l < 2; l++) {           // B: 1024 ops
            int op = tid + l * NTHREADS;
            int r = op >> 3, q = op & 7;
            int cc = cbase + r;
            uint32_t sa = ab + A_BYTES + r * 128 + ((q ^ (r & 7)) << 4);
            cp16(sa, g_wh + (size_t)cc * DIM + k0 + q * 8, cc < NCLS);
        }
    };

    // prologue: fill stages 0..2
    load_stage(0, 0);
    asm volatile("cp.async.commit_group;" ::: "memory");
    load_stage(1, BK);
    asm volatile("cp.async.commit_group;" ::: "memory");
    load_stage(2, 2 * BK);
    asm volatile("cp.async.commit_group;" ::: "memory");

    for (int c = 0; c < NCHUNKS; c++) {
        asm volatile("cp.async.wait_group 2;" ::: "memory");
        __syncthreads();

        // issue next stage first so the transfer overlaps this stage's compute
        if (c + STAGES - 1 < NCHUNKS)
            load_stage((c + STAGES - 1) % STAGES, (c + STAGES - 1) * BK);
        asm volatile("cp.async.commit_group;" ::: "memory");

        const int st = c % STAGES;
        const uint32_t a_stage = sbase + st * STAGE_BYTES;
        const uint32_t b_stage = a_stage + A_BYTES;

        // fp16 chunk accumulators (zeroed per chunk; flushed to f32 below)
        uint32_t hacc[2][4][2];
        #pragma unroll
        for (int i = 0; i < 2; i++)
            #pragma unroll
            for (int j = 0; j < 4; j++) { hacc[i][j][0] = 0u; hacc[i][j][1] = 0u; }

        #pragma unroll
        for (int s = 0; s < 4; s++) {           // 4 x k16 steps per 64-chunk
            const int q = 2 * s + fcq;          // 16B chunk within row
            // B fragments: 2 ldmatrix.x4, each covers 16 n x 16 k
            uint32_t bf[2][4];
            #pragma unroll
            for (int p = 0; p < 2; p++) {
                int r = warp_c + p * 16 + frow;
                uint32_t addr = b_stage + r * 128 + (((q ^ (r & 7)) & 7) << 4);
                ldsm_x4(bf[p], addr);
            }
            // A fragments + MMAs
            #pragma unroll
            for (int mt = 0; mt < 2; mt++) {
                int r = warp_b + mt * 16 + frow;
                uint32_t addr = a_stage + r * 128 + (((q ^ (r & 7)) & 7) << 4);
                uint32_t af[4];
                ldsm_x4(af, addr);
                #pragma unroll
                for (int nt = 0; nt < 4; nt++)
                    mma_f16acc(hacc[mt][nt], af, bf[nt >> 1][nt & 1], bf[nt >> 1][(nt & 1) + 2]);
            }
        }

        // flush fp16 chunk accs into fp32 accumulators
        #pragma unroll
        for (int mt = 0; mt < 2; mt++)
            #pragma unroll
            for (int nt = 0; nt < 4; nt++) {
                float2 f0 = __half22float2(*(__half2*)&hacc[mt][nt][0]);
                float2 f1 = __half22float2(*(__half2*)&hacc[mt][nt][1]);
                acc[mt][nt][0] += f0.x;
                acc[mt][nt][1] += f0.y;
                acc[mt][nt][2] += f1.x;
                acc[mt][nt][3] += f1.y;
            }
        __syncthreads();
    }

    // ---- fused ArcFace epilogue (weights pre-normalized: acc IS the cosine) ----
    #pragma unroll
    for (int mt = 0; mt < 2; mt++) {
        int r = warp_b + mt * 16 + gid;
        int glb0 = bbase + r;
        int glb1 = glb0 + 8;
        int lab0 = s_label[r];
        int lab1 = s_label[r + 8];
        #pragma unroll
        for (int nt = 0; nt < 4; nt++) {
            int c = cbase + warp_c + nt * 8 + 2 * tig;
            if (c >= NCLS) continue;  // c even, NCLS even -> c+1 valid when c < NCLS
            float2 o0, o1;
            o0.x = arcface(acc[mt][nt][0], lab0 == c);
            o0.y = arcface(acc[mt][nt][1], lab0 == c + 1);
            o1.x = arcface(acc[mt][nt][2], lab1 == c);
            o1.y = arcface(acc[mt][nt][3], lab1 == c + 1);
            *(float2*)(out + (size_t)glb0 * NCLS + c) = o0;
            *(float2*)(out + (size_t)glb1 * NCLS + c) = o1;
        }
    }
}

extern "C" void kernel_launch(void* const* d_in, const int* in_sizes, int n_in,
                              void* d_out, int out_size) {
    const float* input  = (const float*)d_in[0];
    const int*   label  = (const int*)d_in[1];
    const float* weight = (const float*)d_in[2];
    float* out = (float*)d_out;

    cudaFuncSetAttribute(k_gemm, cudaFuncAttributeMaxDynamicSharedMemorySize, DYN_SMEM);

    k_norm_input<<<BATCH, 128>>>(input);
    k_wnorm<<<NCLS, 128>>>(weight);
    dim3 grid(BATCH / BM, (NCLS + BN - 1) / BN);
    k_gemm<<<grid, NTHREADS, DYN_SMEM>>>(label, out);
}

// round 8
// speedup vs baseline: 4.4259x; 1.0903x over previous
#include <cuda_runtime.h>
#include <cuda_fp16.h>
#include <cstdint>

// ---------------- problem constants ----------------
#define BATCH 1024
#define DIM   512
#define NCLS  100000

// ---------------- GEMM tiling ----------------
#define BM 128
#define BN 128
#define BK 64                            // fp16: 64 k per chunk
#define NCHUNKS (DIM / BK)               // 8
#define STAGES 4
#define A_BYTES (BM * BK * 2)            // 16384
#define B_BYTES (BN * BK * 2)            // 16384
#define STAGE_BYTES (A_BYTES + B_BYTES)  // 32768
#define DYN_SMEM (STAGES * STAGE_BYTES)  // 131072
#define NTHREADS 512

// scratch (static device arrays — no allocation). Referenced ONLY in device code:
// passing a __device__ symbol as a host-side kernel arg yields the host shadow
// address (the R7 bug).
__device__ __half g_xh[BATCH * DIM];            // normalized input, fp16-rn
__device__ __half g_wh[(size_t)NCLS * DIM];     // normalized weight, fp16-rn (102 MB)

// ---------------- helpers ----------------
__device__ __forceinline__ uint32_t smem_u32(const void* p) {
    uint32_t a;
    asm("{ .reg .u64 t; cvta.to.shared.u64 t, %1; cvt.u32.u64 %0, t; }" : "=r"(a) : "l"(p));
    return a;
}
__device__ __forceinline__ void cp16(uint32_t saddr, const void* g, bool valid) {
    int sz = valid ? 16 : 0;
    asm volatile("cp.async.cg.shared.global.L2::128B [%0], [%1], 16, %2;\n"
                 :: "r"(saddr), "l"(g), "r"(sz) : "memory");
}
__device__ __forceinline__ void ldsm_x4(uint32_t* r, uint32_t addr) {
    asm volatile("ldmatrix.sync.aligned.m8n8.x4.shared.b16 {%0,%1,%2,%3}, [%4];"
                 : "=r"(r[0]), "=r"(r[1]), "=r"(r[2]), "=r"(r[3]) : "r"(addr));
}
// m16n8k16 fp16 MMA, fp16 accumulate
__device__ __forceinline__ void mma_f16acc(uint32_t* d, const uint32_t* a, uint32_t b0, uint32_t b1) {
    asm volatile(
        "mma.sync.aligned.m16n8k16.row.col.f16.f16.f16.f16 "
        "{%0,%1}, {%2,%3,%4,%5}, {%6,%7}, {%0,%1};\n"
        : "+r"(d[0]), "+r"(d[1])
        : "r"(a[0]), "r"(a[1]), "r"(a[2]), "r"(a[3]), "r"(b0), "r"(b1));
}

// ---------------- fused row-normalize -> fp16 (warp per row, MLP=4) ----------------
// Each warp handles one row of 512 floats: lane reads 4x float4 (stride 512B),
// xor-shfl reduce, converts its 16 floats to fp16, 4x 8B coalesced stores.
// DstSel resolves the __device__ destination symbol in device code.
template <int NROWS, int DSTSEL>
__global__ void k_rownorm(const float* __restrict__ src) {
    int warp = (blockIdx.x * blockDim.x + threadIdx.x) >> 5;
    int lane = threadIdx.x & 31;
    if (warp >= NROWS) return;
    const float* row = src + (size_t)warp * DIM;
    float4 v[4];
    #pragma unroll
    for (int i = 0; i < 4; i++) v[i] = *(const float4*)(row + lane * 4 + i * 128);
    float ss = 0.0f;
    #pragma unroll
    for (int i = 0; i < 4; i++)
        ss += v[i].x * v[i].x + v[i].y * v[i].y + v[i].z * v[i].z + v[i].w * v[i].w;
    #pragma unroll
    for (int o = 16; o; o >>= 1) ss += __shfl_xor_sync(0xffffffffu, ss, o);
    float inv = 1.0f / fmaxf(sqrtf(ss), 1e-12f);
    __half* dst = (DSTSEL == 0) ? g_xh : g_wh;   // device-side symbol resolution
    __half* drow = dst + (size_t)warp * DIM;
    #pragma unroll
    for (int i = 0; i < 4; i++) {
        __half2 h0 = __floats2half2_rn(v[i].x * inv, v[i].y * inv);
        __half2 h1 = __floats2half2_rn(v[i].z * inv, v[i].w * inv);
        uint2 pk;
        pk.x = *(uint32_t*)&h0;
        pk.y = *(uint32_t*)&h1;
        *(uint2*)(drow + lane * 4 + i * 128) = pk;
    }
}

// ---------------- ArcFace epilogue math ----------------
__device__ __forceinline__ float arcface(float cosv, bool tgt) {
    if (!tgt) return 30.0f * cosv;
    float s2 = fminf(fmaxf(1.0f - cosv * cosv, 0.0f), 1.0f);
    float sine = sqrtf(s2);
    float phi = cosv * 0.8775825618903728f - sine * 0.479425538604203f;
    phi = (cosv > -0.8775825618903728f) ? phi : (cosv - 7.191383079063045f);
    return 30.0f * phi;
}

// ---------------- pipelined fp16 GEMM (f16 acc, f32 flush every 2 chunks) ----------------
// 512 threads, 16 warps in a 4(b) x 4(c) grid of 32x32 warp tiles.
// SMEM per stage: A[128 rows][64 k] then B[128 rows][64 k], 128B rows, 16B chunks
// swizzled by (q ^ (row&7)).
// grid = (8 btiles, 782 ctiles); x fastest -> 8 CTAs share a weight tile via L2.
__global__ void __launch_bounds__(NTHREADS, 1) k_gemm(
    const int* __restrict__ label,
    float* __restrict__ out)
{
    extern __shared__ __align__(128) char dyn[];
    __shared__ int s_label[BM];

    const int tid = threadIdx.x;
    const int lane = tid & 31;
    const int wid = tid >> 5;
    const int bbase = blockIdx.x * BM;
    const int cbase = blockIdx.y * BN;
    const uint32_t sbase = smem_u32(dyn);

    // warp grid 4(b) x 4(c): each warp computes 32 x 32
    const int warp_b = (wid & 3) * 32;
    const int warp_c = (wid >> 2) * 32;
    const int gid = lane >> 2;
    const int tig = lane & 3;

    // fp16 ldmatrix.x4 lane mapping: row-in-16 = lane&15, 16B k-chunk = lane>>4
    const int frow = lane & 15;
    const int fcq = lane >> 4;

    float acc[2][4][4];
    #pragma unroll
    for (int i = 0; i < 2; i++)
        #pragma unroll
        for (int j = 0; j < 4; j++)
            #pragma unroll
            for (int k = 0; k < 4; k++) acc[i][j][k] = 0.0f;

    if (tid < BM) s_label[tid] = label[bbase + tid];

    // ---- stage loader: 2048 x 16B cp.async, 4 per thread ----
    auto load_stage = [&](int st, int k0) {
        const uint32_t ab = sbase + st * STAGE_BYTES;
        #pragma unroll
        for (int l = 0; l < 2; l++) {           // A: 1024 ops
            int op = tid + l * NTHREADS;
            int r = op >> 3, q = op & 7;        // q: 16B chunk = 8 fp16
            uint32_t sa = ab + r * 128 + ((q ^ (r & 7)) << 4);
            cp16(sa, g_xh + (bbase + r) * DIM + k0 + q * 8, true);
        }
        #pragma unroll
        for (int l = 0; l < 2; l++) {           // B: 1024 ops
            int op = tid + l * NTHREADS;
            int r = op >> 3, q = op & 7;
            int cc = cbase + r;
            uint32_t sa = ab + A_BYTES + r * 128 + ((q ^ (r & 7)) << 4);
            cp16(sa, g_wh + (size_t)cc * DIM + k0 + q * 8, cc < NCLS);
        }
    };

    // prologue: fill stages 0..2
    load_stage(0, 0);
    asm volatile("cp.async.commit_group;" ::: "memory");
    load_stage(1, BK);
    asm volatile("cp.async.commit_group;" ::: "memory");
    load_stage(2, 2 * BK);
    asm volatile("cp.async.commit_group;" ::: "memory");

    // fp16 accumulators live across 2 chunks (128 k), then flush to f32
    uint32_t hacc[2][4][2];

    for (int c = 0; c < NCHUNKS; c++) {
        asm volatile("cp.async.wait_group 2;" ::: "memory");
        __syncthreads();   // also orders iter c-1 smem reads before stage overwrite below

        // issue next stage first so the transfer overlaps this stage's compute
        if (c + STAGES - 1 < NCHUNKS)
            load_stage((c + STAGES - 1) % STAGES, (c + STAGES - 1) * BK);
        asm volatile("cp.async.commit_group;" ::: "memory");

        const int st = c % STAGES;
        const uint32_t a_stage = sbase + st * STAGE_BYTES;
        const uint32_t b_stage = a_stage + A_BYTES;

        if ((c & 1) == 0) {
            #pragma unroll
            for (int i = 0; i < 2; i++)
                #pragma unroll
                for (int j = 0; j < 4; j++) { hacc[i][j][0] = 0u; hacc[i][j][1] = 0u; }
        }

        #pragma unroll
        for (int s = 0; s < 4; s++) {           // 4 x k16 steps per 64-chunk
            const int q = 2 * s + fcq;          // 16B chunk within row
            // B fragments: 2 ldmatrix.x4, each covers 16 n x 16 k
            uint32_t bf[2][4];
            #pragma unroll
            for (int p = 0; p < 2; p++) {
                int r = warp_c + p * 16 + frow;
                uint32_t addr = b_stage + r * 128 + (((q ^ (r & 7)) & 7) << 4);
                ldsm_x4(bf[p], addr);
            }
            // A fragments + MMAs
            #pragma unroll
            for (int mt = 0; mt < 2; mt++) {
                int r = warp_b + mt * 16 + frow;
                uint32_t addr = a_stage + r * 128 + (((q ^ (r & 7)) & 7) << 4);
                uint32_t af[4];
                ldsm_x4(af, addr);
                #pragma unroll
                for (int nt = 0; nt < 4; nt++)
                    mma_f16acc(hacc[mt][nt], af, bf[nt >> 1][nt & 1], bf[nt >> 1][(nt & 1) + 2]);
            }
        }

        if (c & 1) {
            // flush fp16 accs (128 k worth) into fp32 accumulators
            #pragma unroll
            for (int mt = 0; mt < 2; mt++)
                #pragma unroll
                for (int nt = 0; nt < 4; nt++) {
                    float2 f0 = __half22float2(*(__half2*)&hacc[mt][nt][0]);
                    float2 f1 = __half22float2(*(__half2*)&hacc[mt][nt][1]);
                    acc[mt][nt][0] += f0.x;
                    acc[mt][nt][1] += f0.y;
                    acc[mt][nt][2] += f1.x;
                    acc[mt][nt][3] += f1.y;
                }
        }
        // no trailing __syncthreads: next iteration's barrier provides the ordering
    }

    // ---- fused ArcFace epilogue (weights pre-normalized: acc IS the cosine) ----
    #pragma unroll
    for (int mt = 0; mt < 2; mt++) {
        int r = warp_b + mt * 16 + gid;
        int glb0 = bbase + r;
        int glb1 = glb0 + 8;
        int lab0 = s_label[r];
        int lab1 = s_label[r + 8];
        #pragma unroll
        for (int nt = 0; nt < 4; nt++) {
            int c = cbase + warp_c + nt * 8 + 2 * tig;
            if (c >= NCLS) continue;  // c even, NCLS even -> c+1 valid when c < NCLS
            float2 o0, o1;
            o0.x = arcface(acc[mt][nt][0], lab0 == c);
            o0.y = arcface(acc[mt][nt][1], lab0 == c + 1);
            o1.x = arcface(acc[mt][nt][2], lab1 == c);
            o1.y = arcface(acc[mt][nt][3], lab1 == c + 1);
            *(float2*)(out + (size_t)glb0 * NCLS + c) = o0;
            *(float2*)(out + (size_t)glb1 * NCLS + c) = o1;
        }
    }
}

extern "C" void kernel_launch(void* const* d_in, const int* in_sizes, int n_in,
                              void* d_out, int out_size) {
    const float* input  = (const float*)d_in[0];
    const int*   label  = (const int*)d_in[1];
    const float* weight = (const float*)d_in[2];
    float* out = (float*)d_out;

    cudaFuncSetAttribute(k_gemm, cudaFuncAttributeMaxDynamicSharedMemorySize, DYN_SMEM);

    // warp-per-row normalize: 256 threads = 8 rows per block
    k_rownorm<BATCH, 0><<<(BATCH + 7) / 8, 256>>>(input);
    k_rownorm<NCLS, 1><<<(NCLS + 7) / 8, 256>>>(weight);
    dim3 grid(BATCH / BM, (NCLS + BN - 1) / BN);
    k_gemm<<<grid, NTHREADS, DYN_SMEM>>>(label, out);
}

// round 9
// speedup vs baseline: 4.5813x; 1.0351x over previous
#include <cuda_runtime.h>
#include <cuda_fp16.h>
#include <cstdint>

// ---------------- problem constants ----------------
#define BATCH 1024
#define DIM   512
#define NCLS  100000

// ---------------- GEMM tiling ----------------
#define BM 128
#define BN 128
#define BK 64                            // fp16: 64 k per chunk
#define NCHUNKS (DIM / BK)               // 8
#define NBT (BATCH / BM)                 // 8 b-tiles
#define NCT ((NCLS + BN - 1) / BN)       // 782 c-tiles
#define NTILES (NBT * NCT)               // 6256
#define STAGES 4
#define A_BYTES (BM * BK * 2)            // 16384
#define B_BYTES (BN * BK * 2)            // 16384
#define STAGE_BYTES (A_BYTES + B_BYTES)  // 32768
#define DYN_SMEM (STAGES * STAGE_BYTES)  // 131072
#define NTHREADS 512

// scratch (static device arrays — no allocation). Referenced ONLY in device code
// (host-side use of a __device__ symbol yields the shadow address — R7 bug).
__device__ __half g_xh[BATCH * DIM];            // normalized input, fp16-rn
__device__ __half g_wh[(size_t)NCLS * DIM];     // normalized weight, fp16-rn (102 MB)

// ---------------- helpers ----------------
__device__ __forceinline__ uint32_t smem_u32(const void* p) {
    uint32_t a;
    asm("{ .reg .u64 t; cvta.to.shared.u64 t, %1; cvt.u32.u64 %0, t; }" : "=r"(a) : "l"(p));
    return a;
}
__device__ __forceinline__ void cp16(uint32_t saddr, const void* g, bool valid) {
    int sz = valid ? 16 : 0;
    asm volatile("cp.async.cg.shared.global.L2::128B [%0], [%1], 16, %2;\n"
                 :: "r"(saddr), "l"(g), "r"(sz) : "memory");
}
__device__ __forceinline__ void ldsm_x4(uint32_t* r, uint32_t addr) {
    asm volatile("ldmatrix.sync.aligned.m8n8.x4.shared.b16 {%0,%1,%2,%3}, [%4];"
                 : "=r"(r[0]), "=r"(r[1]), "=r"(r[2]), "=r"(r[3]) : "r"(addr));
}
// m16n8k16 fp16 MMA, fp16 accumulate
__device__ __forceinline__ void mma_f16acc(uint32_t* d, const uint32_t* a, uint32_t b0, uint32_t b1) {
    asm volatile(
        "mma.sync.aligned.m16n8k16.row.col.f16.f16.f16.f16 "
        "{%0,%1}, {%2,%3,%4,%5}, {%6,%7}, {%0,%1};\n"
        : "+r"(d[0]), "+r"(d[1])
        : "r"(a[0]), "r"(a[1]), "r"(a[2]), "r"(a[3]), "r"(b0), "r"(b1));
}

// ---------------- fused row-normalize -> fp16 (warp per row, MLP=4) ----------------
template <int NROWS, int DSTSEL>
__global__ void k_rownorm(const float* __restrict__ src) {
    int warp = (blockIdx.x * blockDim.x + threadIdx.x) >> 5;
    int lane = threadIdx.x & 31;
    if (warp >= NROWS) return;
    const float* row = src + (size_t)warp * DIM;
    float4 v[4];
    #pragma unroll
    for (int i = 0; i < 4; i++) v[i] = *(const float4*)(row + lane * 4 + i * 128);
    float ss = 0.0f;
    #pragma unroll
    for (int i = 0; i < 4; i++)
        ss += v[i].x * v[i].x + v[i].y * v[i].y + v[i].z * v[i].z + v[i].w * v[i].w;
    #pragma unroll
    for (int o = 16; o; o >>= 1) ss += __shfl_xor_sync(0xffffffffu, ss, o);
    float inv = 1.0f / fmaxf(sqrtf(ss), 1e-12f);
    __half* dst = (DSTSEL == 0) ? g_xh : g_wh;   // device-side symbol resolution
    __half* drow = dst + (size_t)warp * DIM;
    #pragma unroll
    for (int i = 0; i < 4; i++) {
        __half2 h0 = __floats2half2_rn(v[i].x * inv, v[i].y * inv);
        __half2 h1 = __floats2half2_rn(v[i].z * inv, v[i].w * inv);
        uint2 pk;
        pk.x = *(uint32_t*)&h0;
        pk.y = *(uint32_t*)&h1;
        *(uint2*)(drow + lane * 4 + i * 128) = pk;
    }
}

// ---------------- ArcFace epilogue math ----------------
__device__ __forceinline__ float arcface(float cosv, bool tgt) {
    if (!tgt) return 30.0f * cosv;
    float s2 = fminf(fmaxf(1.0f - cosv * cosv, 0.0f), 1.0f);
    float sine = sqrtf(s2);
    float phi = cosv * 0.8775825618903728f - sine * 0.479425538604203f;
    phi = (cosv > -0.8775825618903728f) ? phi : (cosv - 7.191383079063045f);
    return 30.0f * phi;
}

// ---------------- persistent pipelined fp16 GEMM + fused ArcFace ----------------
// grid = #SMs; each CTA walks tiles t = p, p+G, ... with the cp.async pipeline
// flowing continuously across tile boundaries (flattened chunk index f, stage
// f&3). b-tile is the fastest-varying tile coord so co-resident CTAs share
// weight c-tiles via L2. Epilogue (regs+gmem only) overlaps next tile's loads.
__global__ void __launch_bounds__(NTHREADS, 1) k_gemm(
    const int* __restrict__ label,
    float* __restrict__ out)
{
    extern __shared__ __align__(128) char dyn[];

    const int tid = threadIdx.x;
    const int lane = tid & 31;
    const int wid = tid >> 5;
    const uint32_t sbase = smem_u32(dyn);
    const int p = blockIdx.x;
    const int G = gridDim.x;

    if (p >= NTILES) return;
    const int myTiles = (NTILES - 1 - p) / G + 1;
    const int FMAX = myTiles * NCHUNKS;

    // warp grid 4(b) x 4(c): each warp computes 32 x 32
    const int warp_b = (wid & 3) * 32;
    const int warp_c = (wid >> 2) * 32;
    const int gid = lane >> 2;
    const int tig = lane & 3;

    // fp16 ldmatrix.x4 lane mapping: row-in-16 = lane&15, 16B k-chunk = lane>>4
    const int frow = lane & 15;
    const int fcq = lane >> 4;

    float acc[2][4][4];
    #pragma unroll
    for (int i = 0; i < 2; i++)
        #pragma unroll
        for (int j = 0; j < 4; j++)
            #pragma unroll
            for (int k = 0; k < 4; k++) acc[i][j][k] = 0.0f;

    // ---- flattened-chunk loader: f -> (tile, chunk) ----
    auto load_f = [&](int f) {
        const int t = p + (f >> 3) * G;
        const int k0 = (f & 7) * BK;
        const int bb = (t & (NBT - 1)) * BM;
        const int cb = (t >> 3) * BN;
        const uint32_t ab = sbase + (f & (STAGES - 1)) * STAGE_BYTES;
        #pragma unroll
        for (int l = 0; l < 2; l++) {           // A: 1024 ops
            int op = tid + l * NTHREADS;
            int r = op >> 3, q = op & 7;        // q: 16B chunk = 8 fp16
            uint32_t sa = ab + r * 128 + ((q ^ (r & 7)) << 4);
            cp16(sa, g_xh + (bb + r) * DIM + k0 + q * 8, true);
        }
        #pragma unroll
        for (int l = 0; l < 2; l++) {           // B: 1024 ops
            int op = tid + l * NTHREADS;
            int r = op >> 3, q = op & 7;
            int cc = cb + r;
            uint32_t sa = ab + A_BYTES + r * 128 + ((q ^ (r & 7)) << 4);
            cp16(sa, g_wh + (size_t)cc * DIM + k0 + q * 8, cc < NCLS);
        }
    };

    // prologue: fill 3 stages (paid once per CTA lifetime)
    for (int f = 0; f < 3; f++) {
        if (f < FMAX) load_f(f);
        asm volatile("cp.async.commit_group;" ::: "memory");
    }

    // fp16 accumulators live across 2 chunks (128 k), then flush to f32
    uint32_t hacc[2][4][2];

    for (int f = 0; f < FMAX; f++) {
        asm volatile("cp.async.wait_group 2;" ::: "memory");
        __syncthreads();   // orders prior-iteration smem reads before stage overwrite

        if (f + 3 < FMAX) load_f(f + 3);
        asm volatile("cp.async.commit_group;" ::: "memory");

        const uint32_t a_stage = sbase + (f & (STAGES - 1)) * STAGE_BYTES;
        const uint32_t b_stage = a_stage + A_BYTES;
        const int chunk = f & 7;

        if ((chunk & 1) == 0) {
            #pragma unroll
            for (int i = 0; i < 2; i++)
                #pragma unroll
                for (int j = 0; j < 4; j++) { hacc[i][j][0] = 0u; hacc[i][j][1] = 0u; }
        }

        #pragma unroll
        for (int s = 0; s < 4; s++) {           // 4 x k16 steps per 64-chunk
            const int q = 2 * s + fcq;          // 16B chunk within row
            uint32_t bf[2][4];
            #pragma unroll
            for (int pp = 0; pp < 2; pp++) {
                int r = warp_c + pp * 16 + frow;
                uint32_t addr = b_stage + r * 128 + (((q ^ (r & 7)) & 7) << 4);
                ldsm_x4(bf[pp], addr);
            }
            #pragma unroll
            for (int mt = 0; mt < 2; mt++) {
                int r = warp_b + mt * 16 + frow;
                uint32_t addr = a_stage + r * 128 + (((q ^ (r & 7)) & 7) << 4);
                uint32_t af[4];
                ldsm_x4(af, addr);
                #pragma unroll
                for (int nt = 0; nt < 4; nt++)
                    mma_f16acc(hacc[mt][nt], af, bf[nt >> 1][nt & 1], bf[nt >> 1][(nt & 1) + 2]);
            }
        }

        if (chunk & 1) {
            // flush fp16 accs (128 k worth) into fp32 accumulators
            #pragma unroll
            for (int mt = 0; mt < 2; mt++)
                #pragma unroll
                for (int nt = 0; nt < 4; nt++) {
                    float2 f0 = __half22float2(*(__half2*)&hacc[mt][nt][0]);
                    float2 f1 = __half22float2(*(__half2*)&hacc[mt][nt][1]);
                    acc[mt][nt][0] += f0.x;
                    acc[mt][nt][1] += f0.y;
                    acc[mt][nt][2] += f1.x;
                    acc[mt][nt][3] += f1.y;
                }
        }

        if (chunk == 7) {
            // ---- fused ArcFace epilogue for finished tile (regs+gmem only;
            //      overlaps the already-issued loads of the next tile) ----
            const int t = p + (f >> 3) * G;
            const int bb = (t & (NBT - 1)) * BM;
            const int cb = (t >> 3) * BN;
            #pragma unroll
            for (int mt = 0; mt < 2; mt++) {
                int r = warp_b + mt * 16 + gid;
                int glb0 = bb + r;
                int glb1 = glb0 + 8;
                int lab0 = label[glb0];
                int lab1 = label[glb1];
                #pragma unroll
                for (int nt = 0; nt < 4; nt++) {
                    int c = cb + warp_c + nt * 8 + 2 * tig;
                    if (c >= NCLS) continue;  // c even, NCLS even -> c+1 valid when c < NCLS
                    float2 o0, o1;
                    o0.x = arcface(acc[mt][nt][0], lab0 == c);
                    o0.y = arcface(acc[mt][nt][1], lab0 == c + 1);
                    o1.x = arcface(acc[mt][nt][2], lab1 == c);
                    o1.y = arcface(acc[mt][nt][3], lab1 == c + 1);
                    *(float2*)(out + (size_t)glb0 * NCLS + c) = o0;
                    *(float2*)(out + (size_t)glb1 * NCLS + c) = o1;
                    acc[mt][nt][0] = 0.0f; acc[mt][nt][1] = 0.0f;
                    acc[mt][nt][2] = 0.0f; acc[mt][nt][3] = 0.0f;
                }
            }
        }
    }
}

extern "C" void kernel_launch(void* const* d_in, const int* in_sizes, int n_in,
                              void* d_out, int out_size) {
    const float* input  = (const float*)d_in[0];
    const int*   label  = (const int*)d_in[1];
    const float* weight = (const float*)d_in[2];
    float* out = (float*)d_out;

    cudaFuncSetAttribute(k_gemm, cudaFuncAttributeMaxDynamicSharedMemorySize, DYN_SMEM);

    int nsm = 148;
    cudaDeviceGetAttribute(&nsm, cudaDevAttrMultiProcessorCount, 0);

    // warp-per-row normalize: 256 threads = 8 rows per block
    k_rownorm<BATCH, 0><<<(BATCH + 7) / 8, 256>>>(input);
    k_rownorm<NCLS, 1><<<(NCLS + 7) / 8, 256>>>(weight);
    k_gemm<<<nsm, NTHREADS, DYN_SMEM>>>(label, out);
}